// round 16
// baseline (speedup 1.0000x reference)
#include <cuda_runtime.h>
#include <cuda_fp16.h>
#include <math.h>
#include <stdint.h>

#define BB 32
#define SS 4096

// ---------------- device scratch ----------------
__device__ float g_q[BB * 512];
__device__ float g_scores[BB * SS];
__device__ __align__(16) unsigned short g_Wt[512 * 512];                // W^T [a][e], fp16
__device__ __align__(16) unsigned short g_enc_h[(size_t)BB * SS * 512]; // enc fp16 (written by score, read by ctx)

// ---------------- smem layout (per CTA) ----------------
// A: 2 bufs x 16KB (fp16: 128 rows x 128B (k64))
// B: 2 bufs x 16KB (fp16: 128 rows x 128B (k64))
#define OFF_A    0
#define OFF_B    32768
#define OFF_RED  65536    // 2 x 128 f32 = 1KB
#define SMEM_DYN 66560

// ---------------- asm helpers ----------------
__device__ __forceinline__ uint32_t smem_to_u32(const void* p) {
    uint32_t a;
    asm("{ .reg .u64 t; cvta.to.shared.u64 t, %1; cvt.u32.u64 %0, t; }" : "=r"(a) : "l"(p));
    return a;
}
__device__ __forceinline__ void ldsm4(uint32_t* r, uint32_t addr) {
    asm volatile("ldmatrix.sync.aligned.m8n8.x4.shared.b16 {%0,%1,%2,%3}, [%4];"
                 : "=r"(r[0]), "=r"(r[1]), "=r"(r[2]), "=r"(r[3]) : "r"(addr));
}
__device__ __forceinline__ void mma16816(float* c, const uint32_t* a, uint32_t b0, uint32_t b1) {
    asm volatile("mma.sync.aligned.m16n8k16.row.col.f32.f16.f16.f32 "
                 "{%0,%1,%2,%3}, {%4,%5,%6,%7}, {%8,%9}, {%0,%1,%2,%3};"
                 : "+f"(c[0]), "+f"(c[1]), "+f"(c[2]), "+f"(c[3])
                 : "r"(a[0]), "r"(a[1]), "r"(a[2]), "r"(a[3]), "r"(b0), "r"(b1));
}
__device__ __forceinline__ void cp_async16(uint32_t dst, const void* src) {
    asm volatile("{ .reg .u64 g; cvta.to.global.u64 g, %1; "
                 "cp.async.cg.shared.global [%0], [g], 16; }"
                 :: "r"(dst), "l"(src) : "memory");
}
#define CP_COMMIT() asm volatile("cp.async.commit_group;" ::: "memory")
#define CP_WAIT0()  asm volatile("cp.async.wait_group 0;" ::: "memory")

// fp16x2 pack with round-to-nearest
__device__ __forceinline__ uint32_t cvt_f16x2(float lo, float hi) {
    uint32_t r;
    asm("cvt.rn.f16x2.f32 %0, %1, %2;" : "=r"(r) : "f"(hi), "f"(lo));
    return r;
}

// r = 1/(e^{2x}+1); z = fma(acc, C, qc). ex2 via MUFU, rcp via magic+3 Newton.
#define TANH_C 2.885390081777927f
__device__ __forceinline__ float sig_rcp(float acc, float qc) {
    float z = fmaf(acc, TANH_C, qc);
    z = fminf(z, 126.0f);
    float e2;
    asm("ex2.approx.f32 %0, %1;" : "=f"(e2) : "f"(z));
    float d = e2 + 1.0f;
    float y = __int_as_float(0x7EF311C3 - __float_as_int(d));
    y = y * fmaf(-d, y, 2.0f);
    y = y * fmaf(-d, y, 2.0f);
    y = y * fmaf(-d, y, 2.0f);
    return y;
}

// ---------------------------------------------------------------------------
// prep: W->fp16^T (0..511) | query (512..543) | zero scores (544..607)
// ---------------------------------------------------------------------------
__global__ void prep_kernel(const float* __restrict__ W_s,
                            const float* __restrict__ h,
                            const float* __restrict__ W_h) {
    __shared__ float hs[512];
    const int bid = blockIdx.x;
    const int t = threadIdx.x;
    if (bid < 512) {
        float w = W_s[bid * 512 + t];
        __half wh = __float2half_rn(w);
        g_Wt[(size_t)t * 512 + bid] = *(unsigned short*)&wh;
    } else if (bid < 544) {
        const int b = bid - 512;
        hs[t] = h[b * 512 + t];
        __syncthreads();
        float acc = 0.f;
#pragma unroll 8
        for (int e = 0; e < 512; e++)
            acc = fmaf(hs[e], W_h[e * 512 + t], acc);
        g_q[b * 512 + t] = acc;
    } else {
        ((float4*)g_scores)[(bid - 544) * 512 + t] = make_float4(0.f, 0.f, 0.f, 0.f);
    }
}

// ---------------------------------------------------------------------------
// Score kernel: CTA = (n-quarter 128 attn, m-tile 128 tok, b). 256 thr,
// 8 warps (mw=w&3, nw=w>>2): warp tile m32 x n64. 2 CTAs/SM.
// K: 8 chunks of 64. A: fp32 LDG -> fp16 cvt -> STS (in 2 halves, interleaved
// with MMAs); nq==0 CTAs also STG the converted tile to g_enc_h for ctx.
// B: fp16 cp.async depth-2 ring. ONE __syncthreads per chunk. D = A*B.
// ---------------------------------------------------------------------------
__global__ __launch_bounds__(256, 2)
void score_mma_kernel(const float* __restrict__ enc,
                      const float* __restrict__ v) {
    extern __shared__ __align__(128) char sm[];
    const uint32_t sb = smem_to_u32(sm);
    const int t = threadIdx.x;
    const int w = t >> 5, lid = t & 31;
    const int mw = w & 3, nw = w >> 2;
    const int n0 = blockIdx.x * 128;       // nq fastest: 4 CTAs share A in L2
    const int mtile = blockIdx.y;          // 0..31
    const int b = blockIdx.z;
    const bool wr_enc = (blockIdx.x == 0); // this CTA publishes fp16 A tiles

    const float* encb = enc + ((size_t)b * SS + (size_t)mtile * 128) * 512;
    unsigned short* ench = g_enc_h + ((size_t)b * SS + (size_t)mtile * 128) * 512;

    float acc[2][8][4];
#pragma unroll
    for (int mg = 0; mg < 2; mg++)
#pragma unroll
        for (int j = 0; j < 8; j++)
#pragma unroll
            for (int e = 0; e < 4; e++) acc[mg][j][e] = 0.f;

    const int am = t >> 1, ak = t & 1;     // A roles: row 0..127, k-half 0..1

// B chunk (fp16, k64): 128 rows x 128B = 1024 16B-chunks, 4 per thread
#define ISSUE_B(s_, buf_) do {                                                \
    const uint32_t bb = sb + OFF_B + (buf_) * 16384;                          \
    const int k0_ = (s_) * 64;                                                \
    _Pragma("unroll")                                                         \
    for (int i_ = 0; i_ < 4; i_++) {                                          \
        int idx_ = t + i_ * 256;                                              \
        int r_ = idx_ >> 3;                                                   \
        int cc_ = idx_ & 7;                                                   \
        cp_async16(bb + r_ * 128 + ((cc_ ^ (r_ & 7)) << 4),                   \
                   g_Wt + (size_t)(n0 + r_) * 512 + k0_ + cc_ * 8);           \
    } } while (0)

// A half-chunk: row am, 16 fp32 at k = s*64 + ak*32 + h*16
#define LOAD_A_H(s_, h_, af_) do {                                            \
    const float* p_ = encb + (size_t)am * 512 + (s_) * 64 + ak * 32 + (h_) * 16; \
    af_[0] = *(const float4*)(p_);                                            \
    af_[1] = *(const float4*)(p_ + 4);                                        \
    af_[2] = *(const float4*)(p_ + 8);                                        \
    af_[3] = *(const float4*)(p_ + 12);                                       \
    } while (0)

// Convert 16 fp32 -> fp16, store to smem (swizzled); nq0 also STG to g_enc_h
#define STORE_A_H(s_, buf_, h_, af_) do {                                     \
    char* ab_ = sm + OFF_A + (buf_) * 16384;                                  \
    uint4 v0, v1;                                                             \
    v0.x = cvt_f16x2(af_[0].x, af_[0].y);                                     \
    v0.y = cvt_f16x2(af_[0].z, af_[0].w);                                     \
    v0.z = cvt_f16x2(af_[1].x, af_[1].y);                                     \
    v0.w = cvt_f16x2(af_[1].z, af_[1].w);                                     \
    v1.x = cvt_f16x2(af_[2].x, af_[2].y);                                     \
    v1.y = cvt_f16x2(af_[2].z, af_[2].w);                                     \
    v1.z = cvt_f16x2(af_[3].x, af_[3].y);                                     \
    v1.w = cvt_f16x2(af_[3].z, af_[3].w);                                     \
    int cc0_ = ak * 4 + (h_) * 2;                                             \
    uint32_t base_ = am * 128;                                                \
    *(uint4*)(ab_ + base_ + ((cc0_ ^ (am & 7)) << 4)) = v0;                   \
    *(uint4*)(ab_ + base_ + (((cc0_ + 1) ^ (am & 7)) << 4)) = v1;             \
    if (wr_enc) {                                                             \
        unsigned short* g_ = ench + (size_t)am * 512 + (s_) * 64 + ak * 32 + (h_) * 16; \
        *(uint4*)(g_) = v0;                                                   \
        *(uint4*)(g_ + 8) = v1;                                               \
    } } while (0)

    const int rA = mw * 32 + ((lid >> 3) & 1) * 8 + (lid & 7);  // 0..127
    const int rAx = rA & 7;
    const int cAadd = lid >> 4;
    const int rB = nw * 64 + ((lid >> 4) & 1) * 8 + (lid & 7);  // 0..127
    const int cBadd = (lid >> 3) & 1;

    // ---- prologue: chunk 0 --------------------------------------------------
    ISSUE_B(0, 0);
    CP_COMMIT();
    float4 af[4];
    LOAD_A_H(0, 0, af);
    STORE_A_H(0, 0, 0, af);
    LOAD_A_H(0, 1, af);
    STORE_A_H(0, 0, 1, af);
    CP_WAIT0();
    __syncthreads();

#pragma unroll 1
    for (int c = 0; c < 8; c++) {
        const int buf = c & 1;
        if (c < 7) {
            ISSUE_B(c + 1, buf ^ 1);   // overlaps this chunk's MMAs
            CP_COMMIT();
            LOAD_A_H(c + 1, 0, af);
        }

        const uint32_t ab = sb + OFF_A + buf * 16384;
        const uint32_t bb = sb + OFF_B + buf * 16384;

#pragma unroll
        for (int kk = 0; kk < 4; kk++) {
            const int cA = kk * 2 + cAadd;
            const uint32_t a0off = (uint32_t)rA * 128 + (uint32_t)((cA ^ rAx) << 4);
            const uint32_t a1off = a0off + 16 * 128;      // (rA+16)&7 == rA&7
            const int cB = kk * 2 + cBadd;
            uint32_t boff[4];
            uint32_t bm[4][4];
#pragma unroll
            for (int j = 0; j < 4; j++) {
                int r = rB + j * 16;
                boff[j] = (uint32_t)r * 128 + (uint32_t)((cB ^ (r & 7)) << 4);
                ldsm4(bm[j], bb + boff[j]);
            }
            uint32_t ah0[4], ah1[4];
            ldsm4(ah0, ab + a0off);
            ldsm4(ah1, ab + a1off);

#pragma unroll
            for (int j = 0; j < 4; j++) {
                mma16816(acc[0][2 * j],     ah0, bm[j][0], bm[j][1]);
                mma16816(acc[0][2 * j + 1], ah0, bm[j][2], bm[j][3]);
                mma16816(acc[1][2 * j],     ah1, bm[j][0], bm[j][1]);
                mma16816(acc[1][2 * j + 1], ah1, bm[j][2], bm[j][3]);
            }

            if (kk == 1 && c < 7) {
                STORE_A_H(c + 1, buf ^ 1, 0, af);  // buffer drained in chunk c-1
                LOAD_A_H(c + 1, 1, af);
            }
        }

        if (c < 7) {
            STORE_A_H(c + 1, buf ^ 1, 1, af);
            CP_WAIT0();             // B(c+1) fill complete (overlapped above)
            __syncthreads();        // ONE barrier: publishes A(c+1)+B(c+1)
        }
    }

    // ---- epilogue: score = Sv - 2 * sum(v * 1/(e^{2x}+1)) ----------------
    float qc[8][2], vv[8][2];
    float Sv = 0.f;
#pragma unroll
    for (int j = 0; j < 8; j++) {
        const int c = n0 + nw * 64 + j * 8 + 2 * (lid & 3);
        float2 q2 = *(const float2*)(g_q + b * 512 + c);
        float2 v2 = *(const float2*)(v + c);
        qc[j][0] = q2.x * TANH_C;
        qc[j][1] = q2.y * TANH_C;
        vv[j][0] = v2.x;
        vv[j][1] = v2.y;
        Sv += v2.x + v2.y;
    }

    float part[2][2] = {{0.f, 0.f}, {0.f, 0.f}};
#pragma unroll
    for (int mg = 0; mg < 2; mg++) {
#pragma unroll
        for (int j = 0; j < 8; j++) {
            part[mg][0] = fmaf(vv[j][0], sig_rcp(acc[mg][j][0], qc[j][0]), part[mg][0]);
            part[mg][0] = fmaf(vv[j][1], sig_rcp(acc[mg][j][1], qc[j][1]), part[mg][0]);
            part[mg][1] = fmaf(vv[j][0], sig_rcp(acc[mg][j][2], qc[j][0]), part[mg][1]);
            part[mg][1] = fmaf(vv[j][1], sig_rcp(acc[mg][j][3], qc[j][1]), part[mg][1]);
        }
    }

    float* red = (float*)(sm + OFF_RED);   // [2 nw][128 rows]
    __syncthreads();
#pragma unroll
    for (int mg = 0; mg < 2; mg++)
#pragma unroll
        for (int hf = 0; hf < 2; hf++) {
            float p = fmaf(-2.0f, part[mg][hf], Sv);
            p += __shfl_xor_sync(0xffffffffu, p, 1);
            p += __shfl_xor_sync(0xffffffffu, p, 2);
            if ((lid & 3) == 0)
                red[nw * 128 + mw * 32 + mg * 16 + hf * 8 + (lid >> 2)] = p;
        }
    __syncthreads();
    if (t < 128) {
        float p = red[t] + red[128 + t];
        atomicAdd(&g_scores[b * SS + mtile * 128 + t], p);
    }
}

// ---------------------------------------------------------------------------
// Softmax over S per batch row (applies mask here)
// ---------------------------------------------------------------------------
__global__ void softmax_kernel(const int* __restrict__ mask,
                               float* __restrict__ out_attn) {
    const int b = blockIdx.x;
    const int t = threadIdx.x;   // 256
    __shared__ float red[256];
    const float* sc = g_scores + b * SS;
    const int* mk = mask + b * SS;

    float vals[16];
    float m = -INFINITY;
#pragma unroll
    for (int i = 0; i < 16; i++) {
        int s = t + i * 256;
        vals[i] = (mk[s] != 0) ? -1e9f : sc[s];
        m = fmaxf(m, vals[i]);
    }
    red[t] = m;
    __syncthreads();
    for (int o = 128; o > 0; o >>= 1) {
        if (t < o) red[t] = fmaxf(red[t], red[t + o]);
        __syncthreads();
    }
    m = red[0];
    __syncthreads();

    float sum = 0.f;
#pragma unroll
    for (int i = 0; i < 16; i++) {
        vals[i] = expf(vals[i] - m);
        sum += vals[i];
    }
    red[t] = sum;
    __syncthreads();
    for (int o = 128; o > 0; o >>= 1) {
        if (t < o) red[t] += red[t + o];
        __syncthreads();
    }
    const float inv = 1.f / red[0];
#pragma unroll
    for (int i = 0; i < 16; i++)
        out_attn[b * SS + t + i * 256] = vals[i] * inv;
}

// ---------------------------------------------------------------------------
// ctx[b,e] = sum_s attn[b,s] * enc_fp16[b,s,e]   (grid 64 x 32)
// ---------------------------------------------------------------------------
__global__ void ctx_kernel(const float* __restrict__ attn,
                           float* __restrict__ ctx) {
    const int b = blockIdx.y;
    const int sch = blockIdx.x;
    const int e4 = threadIdx.x * 4;
    const float* ap = attn + b * SS + sch * 64;
    const unsigned short* ep = g_enc_h + ((size_t)b * SS + (size_t)sch * 64) * 512 + e4;

    float4 acc0 = make_float4(0.f, 0.f, 0.f, 0.f);
    float4 acc1 = make_float4(0.f, 0.f, 0.f, 0.f);
#pragma unroll 8
    for (int s = 0; s < 64; s += 2) {
        float a0 = __ldg(&ap[s]);
        float a1 = __ldg(&ap[s + 1]);
        uint2 u0 = *(const uint2*)(ep + (size_t)s * 512);
        uint2 u1 = *(const uint2*)(ep + (size_t)(s + 1) * 512);
        float2 x00 = __half22float2(*(__half2*)&u0.x);
        float2 x01 = __half22float2(*(__half2*)&u0.y);
        float2 x10 = __half22float2(*(__half2*)&u1.x);
        float2 x11 = __half22float2(*(__half2*)&u1.y);
        acc0.x = fmaf(a0, x00.x, acc0.x);
        acc0.y = fmaf(a0, x00.y, acc0.y);
        acc0.z = fmaf(a0, x01.x, acc0.z);
        acc0.w = fmaf(a0, x01.y, acc0.w);
        acc1.x = fmaf(a1, x10.x, acc1.x);
        acc1.y = fmaf(a1, x10.y, acc1.y);
        acc1.z = fmaf(a1, x11.x, acc1.z);
        acc1.w = fmaf(a1, x11.y, acc1.w);
    }
    atomicAdd(&ctx[b * 512 + e4 + 0], acc0.x + acc1.x);
    atomicAdd(&ctx[b * 512 + e4 + 1], acc0.y + acc1.y);
    atomicAdd(&ctx[b * 512 + e4 + 2], acc0.z + acc1.z);
    atomicAdd(&ctx[b * 512 + e4 + 3], acc0.w + acc1.w);
}

// ---------------------------------------------------------------------------
extern "C" void kernel_launch(void* const* d_in, const int* in_sizes, int n_in,
                              void* d_out, int out_size) {
    const float* h    = (const float*)d_in[0];
    const float* enc  = (const float*)d_in[1];
    const int*   mask = (const int*)d_in[2];
    const float* W_h  = (const float*)d_in[3];
    const float* W_s  = (const float*)d_in[4];
    const float* v    = (const float*)d_in[5];

    float* out  = (float*)d_out;
    float* ctx  = out;                 // [32, 512]
    float* attn = out + BB * 512;      // [32, 4096]

    static int attr_done = 0;
    if (!attr_done) {
        cudaFuncSetAttribute(score_mma_kernel,
                             cudaFuncAttributeMaxDynamicSharedMemorySize, SMEM_DYN);
        attr_done = 1;
    }

    cudaMemsetAsync(ctx, 0, BB * 512 * sizeof(float));
    prep_kernel<<<608, 512>>>(W_s, h, W_h);
    score_mma_kernel<<<dim3(4, 32, 32), 256, SMEM_DYN>>>(enc, v);
    softmax_kernel<<<BB, 256>>>(mask, attn);
    ctx_kernel<<<dim3(64, 32), 128>>>(attn, ctx);
}

// round 17
// speedup vs baseline: 1.7578x; 1.7578x over previous
#include <cuda_runtime.h>
#include <cuda_fp16.h>
#include <math.h>
#include <stdint.h>

#define BB 32
#define SS 4096

// ---------------- device scratch ----------------
__device__ float g_q[BB * 512];
__device__ float g_scores[BB * SS];
__device__ __align__(16) unsigned short g_Wt[512 * 512];                // W^T [a][e], fp16
__device__ __align__(16) unsigned short g_enc_h[(size_t)BB * SS * 512]; // enc fp16

// ---------------- smem layout (per CTA) ----------------
// A: 2 bufs x 16KB (fp16: 128 rows x 128B (k64))
// B: 2 bufs x 16KB (fp16: 128 rows x 128B (k64))
#define OFF_A    0
#define OFF_B    32768
#define OFF_RED  65536    // 2 x 128 f32 = 1KB
#define SMEM_DYN 66560

// ---------------- asm helpers ----------------
__device__ __forceinline__ uint32_t smem_to_u32(const void* p) {
    uint32_t a;
    asm("{ .reg .u64 t; cvta.to.shared.u64 t, %1; cvt.u32.u64 %0, t; }" : "=r"(a) : "l"(p));
    return a;
}
__device__ __forceinline__ void ldsm4(uint32_t* r, uint32_t addr) {
    asm volatile("ldmatrix.sync.aligned.m8n8.x4.shared.b16 {%0,%1,%2,%3}, [%4];"
                 : "=r"(r[0]), "=r"(r[1]), "=r"(r[2]), "=r"(r[3]) : "r"(addr));
}
__device__ __forceinline__ void mma16816(float* c, const uint32_t* a, uint32_t b0, uint32_t b1) {
    asm volatile("mma.sync.aligned.m16n8k16.row.col.f32.f16.f16.f32 "
                 "{%0,%1,%2,%3}, {%4,%5,%6,%7}, {%8,%9}, {%0,%1,%2,%3};"
                 : "+f"(c[0]), "+f"(c[1]), "+f"(c[2]), "+f"(c[3])
                 : "r"(a[0]), "r"(a[1]), "r"(a[2]), "r"(a[3]), "r"(b0), "r"(b1));
}
__device__ __forceinline__ void cp_async16(uint32_t dst, const void* src) {
    asm volatile("{ .reg .u64 g; cvta.to.global.u64 g, %1; "
                 "cp.async.cg.shared.global [%0], [g], 16; }"
                 :: "r"(dst), "l"(src) : "memory");
}
#define CP_COMMIT() asm volatile("cp.async.commit_group;" ::: "memory")
#define CP_WAIT0()  asm volatile("cp.async.wait_group 0;" ::: "memory")

// fp16x2 pack with round-to-nearest
__device__ __forceinline__ uint32_t cvt_f16x2(float lo, float hi) {
    uint32_t r;
    asm("cvt.rn.f16x2.f32 %0, %1, %2;" : "=r"(r) : "f"(hi), "f"(lo));
    return r;
}

// r = 1/(e^{2x}+1); z = fma(acc, C, qc). ex2 via MUFU, rcp via magic+3 Newton.
#define TANH_C 2.885390081777927f
__device__ __forceinline__ float sig_rcp(float acc, float qc) {
    float z = fmaf(acc, TANH_C, qc);
    z = fminf(z, 126.0f);
    float e2;
    asm("ex2.approx.f32 %0, %1;" : "=f"(e2) : "f"(z));
    float d = e2 + 1.0f;
    float y = __int_as_float(0x7EF311C3 - __float_as_int(d));
    y = y * fmaf(-d, y, 2.0f);
    y = y * fmaf(-d, y, 2.0f);
    y = y * fmaf(-d, y, 2.0f);
    return y;
}

// ---------------------------------------------------------------------------
// prep: W->fp16^T (0..511) | query (512..543) | zero scores (544..607) |
//       enc fp32 -> fp16 (608..33375)
// ---------------------------------------------------------------------------
__global__ void prep_kernel(const float* __restrict__ W_s,
                            const float* __restrict__ h,
                            const float* __restrict__ W_h,
                            const float* __restrict__ enc) {
    __shared__ float hs[512];
    const int bid = blockIdx.x;
    const int t = threadIdx.x;
    if (bid >= 608) {                      // enc convert: 4 floats per thread
        size_t i = ((size_t)(bid - 608) * 512 + t) * 4;
        float4 f = *(const float4*)(enc + i);
        uint2 hv;
        hv.x = cvt_f16x2(f.x, f.y);
        hv.y = cvt_f16x2(f.z, f.w);
        *(uint2*)(g_enc_h + i) = hv;
    } else if (bid < 512) {
        float w = W_s[bid * 512 + t];
        __half wh = __float2half_rn(w);
        g_Wt[(size_t)t * 512 + bid] = *(unsigned short*)&wh;
    } else if (bid < 544) {
        const int b = bid - 512;
        hs[t] = h[b * 512 + t];
        __syncthreads();
        float acc = 0.f;
#pragma unroll 8
        for (int e = 0; e < 512; e++)
            acc = fmaf(hs[e], W_h[e * 512 + t], acc);
        g_q[b * 512 + t] = acc;
    } else {
        ((float4*)g_scores)[(bid - 544) * 512 + t] = make_float4(0.f, 0.f, 0.f, 0.f);
    }
}

// ---------------------------------------------------------------------------
// Score kernel: CTA = (n-quarter 128 attn, m-tile 128 tok, b). 256 thr,
// 8 warps (mw=w&3, nw=w>>2): warp tile m32 x n64. 2 CTAs/SM.
// K: 8 chunks of 64; A and B BOTH fp16 via cp.async, depth-2 rings,
// one commit group + ONE __syncthreads per chunk. Single pass: D = A*B.
// ---------------------------------------------------------------------------
__global__ __launch_bounds__(256, 2)
void score_mma_kernel(const float* __restrict__ v) {
    extern __shared__ __align__(128) char sm[];
    const uint32_t sb = smem_to_u32(sm);
    const int t = threadIdx.x;
    const int w = t >> 5, lid = t & 31;
    const int mw = w & 3, nw = w >> 2;
    const int n0 = blockIdx.x * 128;       // nq fastest: 4 CTAs share A in L2
    const int mtile = blockIdx.y;          // 0..31
    const int b = blockIdx.z;

    const unsigned short* encb = g_enc_h + ((size_t)b * SS + (size_t)mtile * 128) * 512;

    float acc[2][8][4];
#pragma unroll
    for (int mg = 0; mg < 2; mg++)
#pragma unroll
        for (int j = 0; j < 8; j++)
#pragma unroll
            for (int e = 0; e < 4; e++) acc[mg][j][e] = 0.f;

// A chunk (fp16, k64): 128 rows x 128B = 1024 16B-chunks, 4 per thread
#define ISSUE_A(s_, buf_) do {                                                \
    const uint32_t aa = sb + OFF_A + (buf_) * 16384;                          \
    const int k0_ = (s_) * 64;                                                \
    _Pragma("unroll")                                                         \
    for (int i_ = 0; i_ < 4; i_++) {                                          \
        int idx_ = t + i_ * 256;                                              \
        int r_ = idx_ >> 3;                                                   \
        int cc_ = idx_ & 7;                                                   \
        cp_async16(aa + r_ * 128 + ((cc_ ^ (r_ & 7)) << 4),                   \
                   encb + (size_t)r_ * 512 + k0_ + cc_ * 8);                  \
    } } while (0)

// B chunk (fp16, k64): 128 rows x 128B = 1024 16B-chunks, 4 per thread
#define ISSUE_B(s_, buf_) do {                                                \
    const uint32_t bb = sb + OFF_B + (buf_) * 16384;                          \
    const int k0_ = (s_) * 64;                                                \
    _Pragma("unroll")                                                         \
    for (int i_ = 0; i_ < 4; i_++) {                                          \
        int idx_ = t + i_ * 256;                                              \
        int r_ = idx_ >> 3;                                                   \
        int cc_ = idx_ & 7;                                                   \
        cp_async16(bb + r_ * 128 + ((cc_ ^ (r_ & 7)) << 4),                   \
                   g_Wt + (size_t)(n0 + r_) * 512 + k0_ + cc_ * 8);           \
    } } while (0)

    const int rA = mw * 32 + ((lid >> 3) & 1) * 8 + (lid & 7);  // 0..127
    const int rAx = rA & 7;
    const int cAadd = lid >> 4;
    const int rB = nw * 64 + ((lid >> 4) & 1) * 8 + (lid & 7);  // 0..127
    const int cBadd = (lid >> 3) & 1;

    // ---- prologue: chunk 0 in flight -------------------------------------
    ISSUE_A(0, 0);
    ISSUE_B(0, 0);
    CP_COMMIT();
    CP_WAIT0();
    __syncthreads();

#pragma unroll 1
    for (int c = 0; c < 8; c++) {
        const int buf = c & 1;
        // fills for chunk c+1 overlap this chunk's MMAs (buffer drained in c-1)
        if (c < 7) { ISSUE_A(c + 1, buf ^ 1); ISSUE_B(c + 1, buf ^ 1); CP_COMMIT(); }

        const uint32_t ab = sb + OFF_A + buf * 16384;
        const uint32_t bb = sb + OFF_B + buf * 16384;

#pragma unroll
        for (int kk = 0; kk < 4; kk++) {
            const int cA = kk * 2 + cAadd;
            const uint32_t a0off = (uint32_t)rA * 128 + (uint32_t)((cA ^ rAx) << 4);
            const uint32_t a1off = a0off + 16 * 128;      // (rA+16)&7 == rA&7
            const int cB = kk * 2 + cBadd;
            uint32_t boff[4];
            uint32_t bm[4][4];
#pragma unroll
            for (int j = 0; j < 4; j++) {
                int r = rB + j * 16;
                boff[j] = (uint32_t)r * 128 + (uint32_t)((cB ^ (r & 7)) << 4);
                ldsm4(bm[j], bb + boff[j]);
            }
            uint32_t ah0[4], ah1[4];
            ldsm4(ah0, ab + a0off);
            ldsm4(ah1, ab + a1off);

#pragma unroll
            for (int j = 0; j < 4; j++) {
                mma16816(acc[0][2 * j],     ah0, bm[j][0], bm[j][1]);
                mma16816(acc[0][2 * j + 1], ah0, bm[j][2], bm[j][3]);
                mma16816(acc[1][2 * j],     ah1, bm[j][0], bm[j][1]);
                mma16816(acc[1][2 * j + 1], ah1, bm[j][2], bm[j][3]);
            }
        }

        if (c < 7) {
            CP_WAIT0();             // chunk c+1 fills complete (overlapped)
            __syncthreads();        // ONE barrier: publishes A(c+1)+B(c+1)
        }
    }

    // ---- epilogue: score = Sv - 2 * sum(v * 1/(e^{2x}+1)) ----------------
    float qc[8][2], vv[8][2];
    float Sv = 0.f;
#pragma unroll
    for (int j = 0; j < 8; j++) {
        const int c = n0 + nw * 64 + j * 8 + 2 * (lid & 3);
        float2 q2 = *(const float2*)(g_q + b * 512 + c);
        float2 v2 = *(const float2*)(v + c);
        qc[j][0] = q2.x * TANH_C;
        qc[j][1] = q2.y * TANH_C;
        vv[j][0] = v2.x;
        vv[j][1] = v2.y;
        Sv += v2.x + v2.y;
    }

    float part[2][2] = {{0.f, 0.f}, {0.f, 0.f}};
#pragma unroll
    for (int mg = 0; mg < 2; mg++) {
#pragma unroll
        for (int j = 0; j < 8; j++) {
            part[mg][0] = fmaf(vv[j][0], sig_rcp(acc[mg][j][0], qc[j][0]), part[mg][0]);
            part[mg][0] = fmaf(vv[j][1], sig_rcp(acc[mg][j][1], qc[j][1]), part[mg][0]);
            part[mg][1] = fmaf(vv[j][0], sig_rcp(acc[mg][j][2], qc[j][0]), part[mg][1]);
            part[mg][1] = fmaf(vv[j][1], sig_rcp(acc[mg][j][3], qc[j][1]), part[mg][1]);
        }
    }

    float* red = (float*)(sm + OFF_RED);   // [2 nw][128 rows]
    __syncthreads();
#pragma unroll
    for (int mg = 0; mg < 2; mg++)
#pragma unroll
        for (int hf = 0; hf < 2; hf++) {
            float p = fmaf(-2.0f, part[mg][hf], Sv);
            p += __shfl_xor_sync(0xffffffffu, p, 1);
            p += __shfl_xor_sync(0xffffffffu, p, 2);
            if ((lid & 3) == 0)
                red[nw * 128 + mw * 32 + mg * 16 + hf * 8 + (lid >> 2)] = p;
        }
    __syncthreads();
    if (t < 128) {
        float p = red[t] + red[128 + t];
        atomicAdd(&g_scores[b * SS + mtile * 128 + t], p);
    }
}

// ---------------------------------------------------------------------------
// Softmax over S per batch row (applies mask here)
// ---------------------------------------------------------------------------
__global__ void softmax_kernel(const int* __restrict__ mask,
                               float* __restrict__ out_attn) {
    const int b = blockIdx.x;
    const int t = threadIdx.x;   // 256
    __shared__ float red[256];
    const float* sc = g_scores + b * SS;
    const int* mk = mask + b * SS;

    float vals[16];
    float m = -INFINITY;
#pragma unroll
    for (int i = 0; i < 16; i++) {
        int s = t + i * 256;
        vals[i] = (mk[s] != 0) ? -1e9f : sc[s];
        m = fmaxf(m, vals[i]);
    }
    red[t] = m;
    __syncthreads();
    for (int o = 128; o > 0; o >>= 1) {
        if (t < o) red[t] = fmaxf(red[t], red[t + o]);
        __syncthreads();
    }
    m = red[0];
    __syncthreads();

    float sum = 0.f;
#pragma unroll
    for (int i = 0; i < 16; i++) {
        vals[i] = expf(vals[i] - m);
        sum += vals[i];
    }
    red[t] = sum;
    __syncthreads();
    for (int o = 128; o > 0; o >>= 1) {
        if (t < o) red[t] += red[t + o];
        __syncthreads();
    }
    const float inv = 1.f / red[0];
#pragma unroll
    for (int i = 0; i < 16; i++)
        out_attn[b * SS + t + i * 256] = vals[i] * inv;
}

// ---------------------------------------------------------------------------
// ctx[b,e] = sum_s attn[b,s] * enc_fp16[b,s,e]   (grid 64 x 32)
// ---------------------------------------------------------------------------
__global__ void ctx_kernel(const float* __restrict__ attn,
                           float* __restrict__ ctx) {
    const int b = blockIdx.y;
    const int sch = blockIdx.x;
    const int e4 = threadIdx.x * 4;
    const float* ap = attn + b * SS + sch * 64;
    const unsigned short* ep = g_enc_h + ((size_t)b * SS + (size_t)sch * 64) * 512 + e4;

    float4 acc0 = make_float4(0.f, 0.f, 0.f, 0.f);
    float4 acc1 = make_float4(0.f, 0.f, 0.f, 0.f);
#pragma unroll 8
    for (int s = 0; s < 64; s += 2) {
        float a0 = __ldg(&ap[s]);
        float a1 = __ldg(&ap[s + 1]);
        uint2 u0 = *(const uint2*)(ep + (size_t)s * 512);
        uint2 u1 = *(const uint2*)(ep + (size_t)(s + 1) * 512);
        float2 x00 = __half22float2(*(__half2*)&u0.x);
        float2 x01 = __half22float2(*(__half2*)&u0.y);
        float2 x10 = __half22float2(*(__half2*)&u1.x);
        float2 x11 = __half22float2(*(__half2*)&u1.y);
        acc0.x = fmaf(a0, x00.x, acc0.x);
        acc0.y = fmaf(a0, x00.y, acc0.y);
        acc0.z = fmaf(a0, x01.x, acc0.z);
        acc0.w = fmaf(a0, x01.y, acc0.w);
        acc1.x = fmaf(a1, x10.x, acc1.x);
        acc1.y = fmaf(a1, x10.y, acc1.y);
        acc1.z = fmaf(a1, x11.x, acc1.z);
        acc1.w = fmaf(a1, x11.y, acc1.w);
    }
    atomicAdd(&ctx[b * 512 + e4 + 0], acc0.x + acc1.x);
    atomicAdd(&ctx[b * 512 + e4 + 1], acc0.y + acc1.y);
    atomicAdd(&ctx[b * 512 + e4 + 2], acc0.z + acc1.z);
    atomicAdd(&ctx[b * 512 + e4 + 3], acc0.w + acc1.w);
}

// ---------------------------------------------------------------------------
extern "C" void kernel_launch(void* const* d_in, const int* in_sizes, int n_in,
                              void* d_out, int out_size) {
    const float* h    = (const float*)d_in[0];
    const float* enc  = (const float*)d_in[1];
    const int*   mask = (const int*)d_in[2];
    const float* W_h  = (const float*)d_in[3];
    const float* W_s  = (const float*)d_in[4];
    const float* v    = (const float*)d_in[5];

    float* out  = (float*)d_out;
    float* ctx  = out;                 // [32, 512]
    float* attn = out + BB * 512;      // [32, 4096]

    static int attr_done = 0;
    if (!attr_done) {
        cudaFuncSetAttribute(score_mma_kernel,
                             cudaFuncAttributeMaxDynamicSharedMemorySize, SMEM_DYN);
        attr_done = 1;
    }

    cudaMemsetAsync(ctx, 0, BB * 512 * sizeof(float));
    prep_kernel<<<33376, 512>>>(W_s, h, W_h, enc);
    score_mma_kernel<<<dim3(4, 32, 32), 256, SMEM_DYN>>>(v);
    softmax_kernel<<<BB, 256>>>(mask, attn);
    ctx_kernel<<<dim3(64, 32), 128>>>(attn, ctx);
}